// round 10
// baseline (speedup 1.0000x reference)
#include <cuda_runtime.h>

namespace {
constexpr int kB = 2, kNP = 4, kN = 64, kP = 24, kCin = 16, kC = 32, kT = 96;
constexpr int kRows = kB * kNP * kN * kP;                                // 12288
constexpr long long kAttElems = (long long)kB * kN * kN * kT * kC;       // 25165824
constexpr int kPad = 36;          // smem row stride (floats), 16B-aligned
constexpr float kLog2e = 1.4426950408889634f;
}

__device__ float g_h[kRows * kC];   // h = x @ W, (B*6144, 32) row-major

__device__ __forceinline__ float ex2f(float x) {
    float r; asm("ex2.approx.f32 %0, %1;" : "=f"(r) : "f"(x)); return r;
}
__device__ __forceinline__ float rcpf(float x) {
    float r; asm("rcp.approx.f32 %0, %1;" : "=f"(r) : "f"(x)); return r;
}

// Kernel 1: h = x @ W. One thread = one row x 4-channel quad.
__global__ void h_kernel(const float* __restrict__ x, const float* __restrict__ W) {
    int gid = blockIdx.x * 256 + threadIdx.x;   // 98304 threads
    int q = gid & 7;                            // channel quad (c = 4q..4q+3)
    int row = gid >> 3;
    const float4* xr = (const float4*)(x + row * kCin);
    const float4* Wq = (const float4*)W + q;    // quad of W row k is at k*8+q
    float4 a0 = __ldg(xr), a1 = __ldg(xr + 1), a2 = __ldg(xr + 2), a3 = __ldg(xr + 3);
    float4 acc = make_float4(0.f, 0.f, 0.f, 0.f);
#define FMA4(s, k) { float4 w = __ldg(Wq + (k) * 8); \
    acc.x = fmaf(s, w.x, acc.x); acc.y = fmaf(s, w.y, acc.y); \
    acc.z = fmaf(s, w.z, acc.z); acc.w = fmaf(s, w.w, acc.w); }
    FMA4(a0.x, 0)  FMA4(a0.y, 1)  FMA4(a0.z, 2)  FMA4(a0.w, 3)
    FMA4(a1.x, 4)  FMA4(a1.y, 5)  FMA4(a1.z, 6)  FMA4(a1.w, 7)
    FMA4(a2.x, 8)  FMA4(a2.y, 9)  FMA4(a2.z, 10) FMA4(a2.w, 11)
    FMA4(a3.x, 12) FMA4(a3.y, 13) FMA4(a3.z, 14) FMA4(a3.w, 15)
#undef FMA4
    *(float4*)(g_h + row * kC + q * 4) = acc;
}

// Kernel 2: block = (b,s,p) x 8 i's; warp w owns j in [8w, 8w+8) with h_j
// register-resident; loops over the 8 i's. 8-lane group per j, lane owns 4
// channels. Per-i row-sum partials go to padded smem; 256-thread epilogue
// reduces across warps and applies h_prime = elu(sum * h_flat).
__global__ void __launch_bounds__(256, 4)
att_kernel(const float* __restrict__ adj, float* __restrict__ out) {
    __shared__ float  hs[kN * kPad];       // 64 rows of h[b,s,j,p,:]
    __shared__ float2 as2[8 * kN];         // (0.6*a, 0.4*a), a = adj*log2e
    __shared__ float  part[8 * kC * 9];    // [i_local][c][w] partial row-sums

    const int tid  = threadIdx.x;
    const int warp = tid >> 5;
    const int lane = tid & 31;
    const int lg   = lane & 7;         // channel group: c = 4*lg..4*lg+3
    const int grp  = lane >> 3;        // j within quad (0..3)

    const int p  = blockIdx.x % kP;
    const int bs = blockIdx.x / kP;
    const int s  = bs & 3;
    const int b  = bs >> 2;
    const int i0 = (int)blockIdx.y * 8;

    // Stage h rows (512 float4); row j lives at +j*768 floats in g_h
    const float4* hb = (const float4*)(g_h + (b * 6144 + s * 1536 + p) * 32);
#pragma unroll
    for (int r = 0; r < 2; ++r) {
        int idx = tid + r * 256;            // 0..511
        int jj = idx >> 3, q = idx & 7;
        *(float4*)(hs + jj * kPad + q * 4) = __ldg(hb + jj * 192 + q);
    }
    // Stage pre-scaled adjacency for this block's 8 i's: as2[i_local*64 + j]
#pragma unroll
    for (int r = 0; r < 2; ++r) {
        int idx = tid + r * 256;
        float a = __ldg(adj + (i0 + (idx >> 6)) * kN + (idx & 63)) * kLog2e;
        as2[idx] = make_float2(0.6f * a, 0.4f * a);
    }
    __syncthreads();

    const int jb = warp * 8;               // this warp's j block
    const int jA = jb + grp, jBj = jb + 4 + grp;
    // Register-resident h_j for this lane's two j's
    const float4 hjA = *(const float4*)(hs + jA * kPad + lg * 4);
    const float4 hjB = *(const float4*)(hs + jBj * kPad + lg * 4);

    const int t = p * kNP + s;
    // Store base for i = i0 (advance by i via immediate offsets)
    float* dstA = out + (((long long)(b * kN + i0) * kN + jA) * kT + t) * kC + lg * 4;
    const float2* awA = as2 + jA;
    float* pw = part + lg * 4 * 9 + warp;  // part[i][c][w], c = 4*lg + k

#pragma unroll
    for (int il = 0; il < 8; ++il) {
        const int i = i0 + il;
        const float4 hi = *(const float4*)(hs + i * kPad + lg * 4);  // 1-phase
        const float2 AA = awA[il * 64];
        const float2 AB = awA[il * 64 + 4];

        float a0 = hi.x * hjA.x, a1 = hi.y * hjA.y;
        float a2 = hi.z * hjA.z, a3 = hi.w * hjA.w;
        float b0 = hi.x * hjB.x, b1 = hi.y * hjB.y;
        float b2 = hi.z * hjB.z, b3 = hi.w * hjB.w;

        float ea0 = ex2f(fmaf(AA.x, a0, AA.y * fabsf(a0)));
        float eb0 = ex2f(fmaf(AB.x, b0, AB.y * fabsf(b0)));
        float ea1 = ex2f(fmaf(AA.x, a1, AA.y * fabsf(a1)));
        float eb1 = ex2f(fmaf(AB.x, b1, AB.y * fabsf(b1)));
        float ea2 = ex2f(fmaf(AA.x, a2, AA.y * fabsf(a2)));
        float eb2 = ex2f(fmaf(AB.x, b2, AB.y * fabsf(b2)));
        float ea3 = ex2f(fmaf(AA.x, a3, AA.y * fabsf(a3)));
        float eb3 = ex2f(fmaf(AB.x, b3, AB.y * fabsf(b3)));

        float sa = (ea0 + ea1) + (ea2 + ea3);
        float sb = (eb0 + eb1) + (eb2 + eb3);
        sa += __shfl_xor_sync(0xffffffffu, sa, 1);
        sb += __shfl_xor_sync(0xffffffffu, sb, 1);
        sa += __shfl_xor_sync(0xffffffffu, sa, 2);
        sb += __shfl_xor_sync(0xffffffffu, sb, 2);
        sa += __shfl_xor_sync(0xffffffffu, sa, 4);
        sb += __shfl_xor_sync(0xffffffffu, sb, 4);
        const float ia = rcpf(sa);
        const float ib = rcpf(sb);

        float oa0 = ea0 * ia, oa1 = ea1 * ia, oa2 = ea2 * ia, oa3 = ea3 * ia;
        float ob0 = eb0 * ib, ob1 = eb1 * ib, ob2 = eb2 * ib, ob3 = eb3 * ib;

        float* di = dstA + il * (kN * kT * kC);           // advance i
        *(float4*)di = make_float4(oa0, oa1, oa2, oa3);
        *(float4*)(di + 4 * kT * kC) = make_float4(ob0, ob1, ob2, ob3);

        // Row-sum partial over this warp's 8 j's for channel set of this lane
        float r0 = oa0 + ob0, r1 = oa1 + ob1, r2 = oa2 + ob2, r3 = oa3 + ob3;
        r0 += __shfl_xor_sync(0xffffffffu, r0, 8);
        r1 += __shfl_xor_sync(0xffffffffu, r1, 8);
        r2 += __shfl_xor_sync(0xffffffffu, r2, 8);
        r3 += __shfl_xor_sync(0xffffffffu, r3, 8);
        r0 += __shfl_xor_sync(0xffffffffu, r0, 16);
        r1 += __shfl_xor_sync(0xffffffffu, r1, 16);
        r2 += __shfl_xor_sync(0xffffffffu, r2, 16);
        r3 += __shfl_xor_sync(0xffffffffu, r3, 16);
        if (grp == 0) {
            float* pp = pw + il * (kC * 9);
            pp[0]  = r0;     // part[il][4lg+0][w]
            pp[9]  = r1;
            pp[18] = r2;
            pp[27] = r3;
        }
    }
    __syncthreads();

    // Epilogue: thread = (i_local, c); sum over the 8 warps' partials.
    {
        const int il = tid >> 5;           // 0..7
        const int c  = tid & 31;
        const float* pp = part + (il * kC + c) * 9;
        float tot = ((pp[0] + pp[1]) + (pp[2] + pp[3]))
                  + ((pp[4] + pp[5]) + (pp[6] + pp[7]));
        const int i = i0 + il;
        const int sh = t / kP, ph = t % kP;     // h_flat decomposition of t
        const float hv = g_h[(b * 6144 + sh * 1536 + i * kP + ph) * 32 + c];
        const float hp = tot * hv;
        const float res = hp > 0.f ? hp : expm1f(hp);
        out[kAttElems + ((long long)(b * kN + i) * kT + t) * kC + c] = res;
    }
}

extern "C" void kernel_launch(void* const* d_in, const int* in_sizes, int n_in,
                              void* d_out, int out_size) {
    const float* x   = (const float*)d_in[0];
    const float* adj = (const float*)d_in[1];
    const float* W   = (const float*)d_in[2];
    float* out = (float*)d_out;

    h_kernel<<<(kRows * kC / 4) / 256, 256>>>(x, W);   // 384 blocks

    dim3 grid(kB * kNP * kP, kN / 8);   // (192, 8)
    att_kernel<<<grid, 256>>>(adj, out);
}

// round 11
// speedup vs baseline: 1.1514x; 1.1514x over previous
#include <cuda_runtime.h>

namespace {
constexpr int kB = 2, kNP = 4, kN = 64, kP = 24, kCin = 16, kC = 32, kT = 96;
constexpr long long kAttElems = (long long)kB * kN * kN * kT * kC;       // 25165824
constexpr int kPad = 36;          // hs row stride (floats), 16B-aligned
constexpr int kXPad = 20;         // x-tile row stride (floats), 16B-aligned
constexpr float kLog2e = 1.4426950408889634f;
}

__device__ __forceinline__ float ex2f(float x) {
    float r; asm("ex2.approx.f32 %0, %1;" : "=f"(r) : "f"(x)); return r;
}
__device__ __forceinline__ float rcpf(float x) {
    float r; asm("rcp.approx.f32 %0, %1;" : "=f"(r) : "f"(x)); return r;
}

// Single fused kernel. Block = (b,s,p) x 8 i's. Stages x-tile + W, computes
// the 64x32 h-tile and 8 h_flat rows in-block (same FMA order as the old
// h_kernel), then runs the proven R8 main loop: warp = (b,s,i,p), 8-lane
// group owns one j (4 j's/iter, 16 iters), lane owns 4 channels.
__global__ void __launch_bounds__(256, 6)
att_kernel(const float* __restrict__ x, const float* __restrict__ adj,
           const float* __restrict__ W, float* __restrict__ out) {
    __shared__ float  Ws[kCin * kC];       // W verbatim copy (512 floats)
    __shared__ float  xs[kN * kXPad];      // x rows (b,s,j,p,:) for j=0..63
    __shared__ float  xf[8 * kXPad];       // x rows (b,sh,i,ph,:) for the 8 i's
    __shared__ float  hs[kN * kPad];       // h tile rows
    __shared__ float  hf[8 * kPad];        // h_flat rows for the 8 i's
    __shared__ float2 as2[8 * kN];         // (0.6*a, 0.4*a), a = adj*log2e

    const int tid  = threadIdx.x;
    const int warp = tid >> 5;
    const int lane = tid & 31;
    const int lg   = lane & 7;         // channel group: c = 4*lg..4*lg+3
    const int grp  = lane >> 3;        // j subgroup within warp (0..3)

    const int p  = blockIdx.x % kP;
    const int bs = blockIdx.x / kP;
    const int s  = bs & 3;
    const int b  = bs >> 2;
    const int i0 = (int)blockIdx.y * 8;

    const int t  = p * kNP + s;
    const int sh = t / kP, ph = t % kP;    // h_flat decomposition of t

    // ---- Stage: W, x-tile, xf rows, adj ----
    if (tid < 128)   // W copy: 128 float4
        *(float4*)(Ws + tid * 4) = __ldg((const float4*)W + tid);

    {   // x rows for all 64 j at (b,s,p): 256 float4, one per thread
        const int j = tid >> 2, q = tid & 3;
        const float* src = x + (((b * 4 + s) * 1536) + j * 24 + p) * 16 + q * 4;
        *(float4*)(xs + j * kXPad + q * 4) = __ldg((const float4*)src);
    }
    if (tid < 32) {  // x rows for h_flat: 8 rows x 4 quads
        const int r = tid >> 2, q = tid & 3;
        const float* src = x + (((b * 4 + sh) * 1536) + (i0 + r) * 24 + ph) * 16 + q * 4;
        *(float4*)(xf + r * kXPad + q * 4) = __ldg((const float4*)src);
    }
#pragma unroll
    for (int r = 0; r < 2; ++r) {   // adj, pre-scaled
        int idx = tid + r * 256;
        float a = __ldg(adj + (i0 + (idx >> 6)) * kN + (idx & 63)) * kLog2e;
        as2[idx] = make_float2(0.6f * a, 0.4f * a);
    }
    __syncthreads();

    // ---- Compute h tile: thread does rows j and j+32 for channel quad q ----
    {
        const int q = tid & 7, j = tid >> 3;     // j in [0,32)
        float4 acc0 = make_float4(0.f, 0.f, 0.f, 0.f);
        float4 acc1 = make_float4(0.f, 0.f, 0.f, 0.f);
        const float* x0 = xs + j * kXPad;
        const float* x1 = xs + (j + 32) * kXPad;
#pragma unroll
        for (int k = 0; k < kCin; ++k) {
            const float4 w4 = *(const float4*)(Ws + k * kC + q * 4);
            const float a = x0[k], c = x1[k];
            acc0.x = fmaf(a, w4.x, acc0.x); acc0.y = fmaf(a, w4.y, acc0.y);
            acc0.z = fmaf(a, w4.z, acc0.z); acc0.w = fmaf(a, w4.w, acc0.w);
            acc1.x = fmaf(c, w4.x, acc1.x); acc1.y = fmaf(c, w4.y, acc1.y);
            acc1.z = fmaf(c, w4.z, acc1.z); acc1.w = fmaf(c, w4.w, acc1.w);
        }
        *(float4*)(hs + j * kPad + q * 4) = acc0;
        *(float4*)(hs + (j + 32) * kPad + q * 4) = acc1;
    }
    // ---- Compute h_flat values: thread = (i_local, c) ----
    {
        const int il = tid >> 5, c = tid & 31;
        const float* xr = xf + il * kXPad;
        float acc = 0.f;
#pragma unroll
        for (int k = 0; k < kCin; ++k)
            acc = fmaf(xr[k], Ws[k * kC + c], acc);
        hf[il * kPad + c] = acc;
    }
    __syncthreads();

    // ---- Main loop (R8 verbatim) ----
    const int i = i0 + warp;
    const float4 hiv = *(const float4*)(hs + i * kPad + lg * 4);

    float* dstb = out + (((long long)(b * kN + i) * kN + grp) * kT + t) * kC + lg * 4;
    const float*  hrb = hs + grp * kPad + lg * 4;
    const float2* awb = as2 + warp * kN + grp;

    float rs0 = 0.f, rs1 = 0.f, rs2 = 0.f, rs3 = 0.f;
#pragma unroll
    for (int jg = 0; jg < 16; ++jg) {
        const float4 hj = *(const float4*)(hrb + jg * (4 * kPad));
        const float2 A = awb[jg * 4];

        float x0 = hiv.x * hj.x, x1 = hiv.y * hj.y;
        float x2 = hiv.z * hj.z, x3 = hiv.w * hj.w;
        float e0 = ex2f(fmaf(A.x, x0, A.y * fabsf(x0)));
        float e1 = ex2f(fmaf(A.x, x1, A.y * fabsf(x1)));
        float e2 = ex2f(fmaf(A.x, x2, A.y * fabsf(x2)));
        float e3 = ex2f(fmaf(A.x, x3, A.y * fabsf(x3)));

        float sl = (e0 + e1) + (e2 + e3);
        sl += __shfl_xor_sync(0xffffffffu, sl, 1);
        sl += __shfl_xor_sync(0xffffffffu, sl, 2);
        sl += __shfl_xor_sync(0xffffffffu, sl, 4);
        const float inv = rcpf(sl);

        float o0 = e0 * inv, o1 = e1 * inv, o2 = e2 * inv, o3 = e3 * inv;
        rs0 += o0; rs1 += o1; rs2 += o2; rs3 += o3;
        *(float4*)(dstb + jg * (4 * kT * kC)) = make_float4(o0, o1, o2, o3);
    }

    // Reduce rsum across the 4 j-subgroups (lane bits 3,4)
    rs0 += __shfl_xor_sync(0xffffffffu, rs0, 8);
    rs1 += __shfl_xor_sync(0xffffffffu, rs1, 8);
    rs2 += __shfl_xor_sync(0xffffffffu, rs2, 8);
    rs3 += __shfl_xor_sync(0xffffffffu, rs3, 8);
    rs0 += __shfl_xor_sync(0xffffffffu, rs0, 16);
    rs1 += __shfl_xor_sync(0xffffffffu, rs1, 16);
    rs2 += __shfl_xor_sync(0xffffffffu, rs2, 16);
    rs3 += __shfl_xor_sync(0xffffffffu, rs3, 16);

    if (grp == 0) {   // lanes 0..7 hold full sums for channels 4*lg..4*lg+3
        const float4 hv = *(const float4*)(hf + warp * kPad + lg * 4);
        float h0 = rs0 * hv.x, h1 = rs1 * hv.y, h2 = rs2 * hv.z, h3 = rs3 * hv.w;
        float4 r;
        r.x = h0 > 0.f ? h0 : expm1f(h0);
        r.y = h1 > 0.f ? h1 : expm1f(h1);
        r.z = h2 > 0.f ? h2 : expm1f(h2);
        r.w = h3 > 0.f ? h3 : expm1f(h3);
        *(float4*)(out + kAttElems +
                   ((long long)(b * kN + i) * kT + t) * kC + lg * 4) = r;
    }
}

extern "C" void kernel_launch(void* const* d_in, const int* in_sizes, int n_in,
                              void* d_out, int out_size) {
    const float* x   = (const float*)d_in[0];
    const float* adj = (const float*)d_in[1];
    const float* W   = (const float*)d_in[2];
    float* out = (float*)d_out;

    dim3 grid(kB * kNP * kP, kN / 8);   // (192, 8)
    att_kernel<<<grid, 256>>>(x, adj, W, out);
}